// round 2
// baseline (speedup 1.0000x reference)
#include <cuda_runtime.h>

// Problem constants
#define B_  4
#define N_  7
#define L_  512
#define S_  512
#define H_  8
#define E_  64
#define D_  64

constexpr int TILE    = 64;
constexpr int THREADS = 256;

// Shared memory layout (floats)
constexpr int QP = 65;  // scalar-access pads (stride 65 -> 2-way worst case)
constexpr int KP = 65;
constexpr int VP = 68;  // float4-access pads (stride 68 floats = 272B, 16B aligned)
constexpr int PP = 68;

constexpr int Q_OFF = 0;
constexpr int K_OFF = Q_OFF + TILE * QP;
constexpr int V_OFF = K_OFF + TILE * KP;
constexpr int P_OFF = V_OFF + TILE * VP;
constexpr int SMEM_FLOATS = P_OFF + TILE * PP;
constexpr int SMEM_BYTES  = SMEM_FLOATS * 4;   // 68096 B

__global__ __launch_bounds__(THREADS, 1)
void attn_flash_fp32_kernel(const float* __restrict__ Qg,
                            const float* __restrict__ Kg,
                            const float* __restrict__ Vg,
                            float* __restrict__ Og) {
    extern __shared__ float sm[];
    float* Qs = sm + Q_OFF;
    float* Ks = sm + K_OFF;
    float* Vs = sm + V_OFF;
    float* Ps = sm + P_OFF;

    const int tid = threadIdx.x;
    const int tx  = tid & 15;   // column-group 0..15 (owns cols 4*tx..4*tx+3)
    const int ty  = tid >> 4;   // row-group    0..15 (owns rows 4*ty..4*ty+3)

    const int l0 = blockIdx.x * TILE;        // Q-row tile
    const int bn = blockIdx.y >> 3;          // fused (b*N + n), 0..27
    const int h  = blockIdx.y & 7;

    // Global bases for this head. Layouts: [BN, L/S, H, E/D], innermost contiguous.
    const int qbase = bn * (L_ * H_ * E_) + h * E_;
    const int kbase = bn * (S_ * H_ * E_) + h * E_;
    const int vbase = bn * (S_ * H_ * D_) + h * D_;
    const int qrow_stride = H_ * E_;   // 512
    const int krow_stride = H_ * E_;   // 512
    const int vrow_stride = H_ * D_;   // 512

    // ---- Load Q tile 64x64 (float4 global, scalar smem stores) ----
    #pragma unroll
    for (int c = tid; c < TILE * 16; c += THREADS) {
        const int r  = c >> 4;
        const int e4 = (c & 15) << 2;
        float4 v = *reinterpret_cast<const float4*>(
            Qg + qbase + (l0 + r) * qrow_stride + e4);
        float* dst = Qs + r * QP + e4;
        dst[0] = v.x; dst[1] = v.y; dst[2] = v.z; dst[3] = v.w;
    }

    // Per-thread online-softmax state for 4 rows, 4 output columns
    float mrow[4], lrow[4];
    float Oacc[4][4];
    #pragma unroll
    for (int i = 0; i < 4; i++) {
        mrow[i] = -1e30f;
        lrow[i] = 0.0f;
        #pragma unroll
        for (int j = 0; j < 4; j++) Oacc[i][j] = 0.0f;
    }

    const float scale = 0.125f;   // 1/sqrt(64)

    for (int s0 = 0; s0 < S_; s0 += TILE) {
        // Protects: Q ready (iter 0); prior-iter P·V reads of Ks/Vs/Ps complete.
        __syncthreads();

        // ---- Load K tile and V tile (64x64 each) ----
        #pragma unroll
        for (int c = tid; c < TILE * 16; c += THREADS) {
            const int r  = c >> 4;
            const int e4 = (c & 15) << 2;
            float4 kv = *reinterpret_cast<const float4*>(
                Kg + kbase + (s0 + r) * krow_stride + e4);
            float* kdst = Ks + r * KP + e4;
            kdst[0] = kv.x; kdst[1] = kv.y; kdst[2] = kv.z; kdst[3] = kv.w;

            float4 vv = *reinterpret_cast<const float4*>(
                Vg + vbase + (s0 + r) * vrow_stride + e4);
            // VP stride is float4-aligned: vectored store
            *reinterpret_cast<float4*>(Vs + r * VP + e4) = vv;
        }
        __syncthreads();

        // ---- Scores: C[4][4] = Q(4 rows) . K^T(4 cols), K-dim = 64 ----
        float C[4][4];
        #pragma unroll
        for (int i = 0; i < 4; i++)
            #pragma unroll
            for (int j = 0; j < 4; j++) C[i][j] = 0.0f;

        const float* qrow = Qs + (4 * ty) * QP;
        const float* krow = Ks + (4 * tx) * KP;
        #pragma unroll 8
        for (int e = 0; e < E_; e++) {
            const float a0 = qrow[0 * QP + e];
            const float a1 = qrow[1 * QP + e];
            const float a2 = qrow[2 * QP + e];
            const float a3 = qrow[3 * QP + e];
            const float b0 = krow[0 * KP + e];
            const float b1 = krow[1 * KP + e];
            const float b2 = krow[2 * KP + e];
            const float b3 = krow[3 * KP + e];
            C[0][0] = fmaf(a0, b0, C[0][0]); C[0][1] = fmaf(a0, b1, C[0][1]);
            C[0][2] = fmaf(a0, b2, C[0][2]); C[0][3] = fmaf(a0, b3, C[0][3]);
            C[1][0] = fmaf(a1, b0, C[1][0]); C[1][1] = fmaf(a1, b1, C[1][1]);
            C[1][2] = fmaf(a1, b2, C[1][2]); C[1][3] = fmaf(a1, b3, C[1][3]);
            C[2][0] = fmaf(a2, b0, C[2][0]); C[2][1] = fmaf(a2, b1, C[2][1]);
            C[2][2] = fmaf(a2, b2, C[2][2]); C[2][3] = fmaf(a2, b3, C[2][3]);
            C[3][0] = fmaf(a3, b0, C[3][0]); C[3][1] = fmaf(a3, b1, C[3][1]);
            C[3][2] = fmaf(a3, b2, C[3][2]); C[3][3] = fmaf(a3, b3, C[3][3]);
        }

        // ---- Online softmax per row (row stats shared by the 16 tx-lanes) ----
        #pragma unroll
        for (int i = 0; i < 4; i++) {
            float c0 = C[i][0] * scale, c1 = C[i][1] * scale;
            float c2 = C[i][2] * scale, c3 = C[i][3] * scale;
            float mx = fmaxf(fmaxf(c0, c1), fmaxf(c2, c3));
            // reduce max across the 16 lanes of this row
            #pragma unroll
            for (int off = 8; off >= 1; off >>= 1)
                mx = fmaxf(mx, __shfl_xor_sync(0xffffffffu, mx, off));
            const float mnew  = fmaxf(mrow[i], mx);
            const float alpha = __expf(mrow[i] - mnew);
            const float p0 = __expf(c0 - mnew);
            const float p1 = __expf(c1 - mnew);
            const float p2 = __expf(c2 - mnew);
            const float p3 = __expf(c3 - mnew);
            float psum = p0 + p1 + p2 + p3;
            #pragma unroll
            for (int off = 8; off >= 1; off >>= 1)
                psum += __shfl_xor_sync(0xffffffffu, psum, off);
            lrow[i] = lrow[i] * alpha + psum;
            mrow[i] = mnew;
            Oacc[i][0] *= alpha; Oacc[i][1] *= alpha;
            Oacc[i][2] *= alpha; Oacc[i][3] *= alpha;
            // write probabilities for the P.V GEMM
            float4 pv = make_float4(p0, p1, p2, p3);
            *reinterpret_cast<float4*>(Ps + (4 * ty + i) * PP + 4 * tx) = pv;
        }
        __syncthreads();   // Ps ready

        // ---- O += P(4 rows) . V  over s=0..63, output cols 4*tx..4*tx+3 ----
        const float* prow = Ps + (4 * ty) * PP;
        #pragma unroll 8
        for (int s = 0; s < TILE; s++) {
            const float4 bv = *reinterpret_cast<const float4*>(Vs + s * VP + 4 * tx);
            const float a0 = prow[0 * PP + s];
            const float a1 = prow[1 * PP + s];
            const float a2 = prow[2 * PP + s];
            const float a3 = prow[3 * PP + s];
            Oacc[0][0] = fmaf(a0, bv.x, Oacc[0][0]); Oacc[0][1] = fmaf(a0, bv.y, Oacc[0][1]);
            Oacc[0][2] = fmaf(a0, bv.z, Oacc[0][2]); Oacc[0][3] = fmaf(a0, bv.w, Oacc[0][3]);
            Oacc[1][0] = fmaf(a1, bv.x, Oacc[1][0]); Oacc[1][1] = fmaf(a1, bv.y, Oacc[1][1]);
            Oacc[1][2] = fmaf(a1, bv.z, Oacc[1][2]); Oacc[1][3] = fmaf(a1, bv.w, Oacc[1][3]);
            Oacc[2][0] = fmaf(a2, bv.x, Oacc[2][0]); Oacc[2][1] = fmaf(a2, bv.y, Oacc[2][1]);
            Oacc[2][2] = fmaf(a2, bv.z, Oacc[2][2]); Oacc[2][3] = fmaf(a2, bv.w, Oacc[2][3]);
            Oacc[3][0] = fmaf(a3, bv.x, Oacc[3][0]); Oacc[3][1] = fmaf(a3, bv.y, Oacc[3][1]);
            Oacc[3][2] = fmaf(a3, bv.z, Oacc[3][2]); Oacc[3][3] = fmaf(a3, bv.w, Oacc[3][3]);
        }
    }

    // ---- Epilogue: normalize and store. Output layout [BN, L, H, D]. ----
    const int obase = bn * (L_ * H_ * D_) + h * D_;
    #pragma unroll
    for (int i = 0; i < 4; i++) {
        const float inv_l = 1.0f / lrow[i];
        float4 o;
        o.x = Oacc[i][0] * inv_l;
        o.y = Oacc[i][1] * inv_l;
        o.z = Oacc[i][2] * inv_l;
        o.w = Oacc[i][3] * inv_l;
        *reinterpret_cast<float4*>(
            Og + obase + (l0 + 4 * ty + i) * (H_ * D_) + 4 * tx) = o;
    }
}

extern "C" void kernel_launch(void* const* d_in, const int* in_sizes, int n_in,
                              void* d_out, int out_size) {
    const float* Q = (const float*)d_in[0];
    const float* K = (const float*)d_in[1];
    const float* V = (const float*)d_in[2];
    float* O = (float*)d_out;

    cudaFuncSetAttribute(attn_flash_fp32_kernel,
                         cudaFuncAttributeMaxDynamicSharedMemorySize, SMEM_BYTES);

    dim3 grid(L_ / TILE, B_ * N_ * H_);   // (8, 224)
    attn_flash_fp32_kernel<<<grid, THREADS, SMEM_BYTES>>>(Q, K, V, O);
}

// round 4
// speedup vs baseline: 3.3432x; 3.3432x over previous
#include <cuda_runtime.h>
#include <stdint.h>

// Problem constants
#define B_  4
#define N_  7
#define L_  512
#define S_  512
#define H_  8
#define E_  64
#define D_  64

constexpr int M_TILE  = 128;     // Q rows per CTA
constexpr int S_TILE  = 64;      // keys per iteration
constexpr int THREADS = 256;     // 8 warps, each owns 16 Q rows
constexpr int NSTEPS  = S_ / S_TILE;

// smem strides in 32-bit words, per-buffer to kill fragment bank conflicts:
//  K,P rows indexed by g (lane>>2):  bank = 4g + t  -> stride % 32 == 4  (68)
//  V rows indexed by t (lane&3):     bank = 8t + g  -> stride % 32 == 8  (72)
constexpr int KS = 68;
constexpr int VS = 72;
constexpr int PS = 68;

constexpr int K_OFF = 0;
constexpr int V_OFF = K_OFF + S_TILE * KS;     // 4352
constexpr int P_OFF = V_OFF + S_TILE * VS;     // 8960  (also Q staging area)
constexpr int SMEM_WORDS = P_OFF + M_TILE * PS;
constexpr int SMEM_BYTES = SMEM_WORDS * 4;     // 70656 B -> 2 CTAs/SM

// f32 -> tf32 (round-to-nearest)
__device__ __forceinline__ uint32_t f2tf(float f) {
    uint32_t r;
    asm("cvt.rna.tf32.f32 %0, %1;" : "=r"(r) : "f"(f));
    return r;
}
__device__ __forceinline__ uint4 cvt4(float4 v) {
    return make_uint4(f2tf(v.x), f2tf(v.y), f2tf(v.z), f2tf(v.w));
}

// D = A(16x8) * B(8x8) + C, tf32 inputs, fp32 accum  (baseline PTX, sm_80+)
__device__ __forceinline__ void mma_tf32(float* d, const uint32_t* a,
                                         uint32_t b0, uint32_t b1,
                                         const float* c) {
    asm volatile(
        "mma.sync.aligned.m16n8k8.row.col.f32.tf32.tf32.f32 "
        "{%0,%1,%2,%3}, {%4,%5,%6,%7}, {%8,%9}, {%10,%11,%12,%13};"
        : "=f"(d[0]), "=f"(d[1]), "=f"(d[2]), "=f"(d[3])
        : "r"(a[0]), "r"(a[1]), "r"(a[2]), "r"(a[3]),
          "r"(b0), "r"(b1),
          "f"(c[0]), "f"(c[1]), "f"(c[2]), "f"(c[3]));
}

// exp(0.125*s) entirely on the FMA/ALU pipes (no MUFU)
__device__ __forceinline__ float pexp(float s) {
    float t = s * 0.18033688f;               // 0.125 * log2(e)
    t = fmaxf(t, -120.0f);
    float z = t + 12582912.0f;               // round-to-nearest magic
    int   n = __float_as_int(z) - 0x4B400000;
    float f = t - (z - 12582912.0f);         // f in [-0.5, 0.5]
    float p = 1.3333558e-3f;
    p = fmaf(p, f, 9.6181291e-3f);
    p = fmaf(p, f, 5.5504109e-2f);
    p = fmaf(p, f, 2.4022651e-1f);
    p = fmaf(p, f, 6.9314718e-1f);
    p = fmaf(p, f, 1.0f);
    return __int_as_float(__float_as_int(p) + (n << 23));
}

__global__ __launch_bounds__(THREADS, 2)
void attn_hmma_tf32_kernel(const float* __restrict__ Qg,
                           const float* __restrict__ Kg,
                           const float* __restrict__ Vg,
                           float* __restrict__ Og) {
    extern __shared__ uint32_t sm[];
    uint32_t* Ksm = sm + K_OFF;
    uint32_t* Vsm = sm + V_OFF;
    uint32_t* Psm = sm + P_OFF;

    const int tid  = threadIdx.x;
    const int lane = tid & 31;
    const int w    = tid >> 5;       // warp 0..7, owns rows w*16 .. w*16+15
    const int g    = lane >> 2;      // groupID (row within fragment)
    const int t    = lane & 3;       // threadID-in-group

    const int l0 = blockIdx.x * M_TILE;
    const int bn = blockIdx.y >> 3;
    const int h  = blockIdx.y & 7;

    const int qbase = bn * (L_ * H_ * E_) + h * E_;
    const int kbase = bn * (S_ * H_ * E_) + h * E_;
    const int vbase = bn * (S_ * H_ * D_) + h * D_;

    // ---- Stage this warp's 16 Q rows into P region (warp-private), tf32 ----
    {
        const float* qsrc = Qg + qbase + (l0 + w * 16) * 512;
        #pragma unroll
        for (int j = 0; j < 8; ++j) {
            const int idx = lane + j * 32;          // 0..255
            const int r   = idx >> 4;               // 0..15
            const int c4  = (idx & 15) << 2;        // 0..60
            float4 v = *reinterpret_cast<const float4*>(qsrc + r * 512 + c4);
            *reinterpret_cast<uint4*>(&Psm[(w * 16 + r) * PS + c4]) = cvt4(v);
        }
    }
    __syncwarp();

    // ---- Resident A fragments of Q: Qa[kc][0..3], kc = E/8 chunks ----
    uint32_t Qa[8][4];
    {
        const uint32_t* r0 = &Psm[(w * 16 + g) * PS];
        const uint32_t* r1 = r0 + 8 * PS;
        #pragma unroll
        for (int kc = 0; kc < 8; ++kc) {
            Qa[kc][0] = r0[kc * 8 + t];
            Qa[kc][1] = r1[kc * 8 + t];
            Qa[kc][2] = r0[kc * 8 + t + 4];
            Qa[kc][3] = r1[kc * 8 + t + 4];
        }
    }
    __syncwarp();

    // O accumulators: 8 n-frags (d columns) x 4 regs; softmax denominators
    float Oc[8][4];
    #pragma unroll
    for (int nf = 0; nf < 8; ++nf)
        #pragma unroll
        for (int i = 0; i < 4; ++i) Oc[nf][i] = 0.0f;
    float lsum0 = 0.0f, lsum1 = 0.0f;

    for (int it = 0; it < NSTEPS; ++it) {
        const int s0 = it * S_TILE;
        __syncthreads();    // prior tile's K/V reads complete

        // ---- Cooperative K/V tile load (fp32 -> tf32 in smem) ----
        #pragma unroll
        for (int j = 0; j < 4; ++j) {
            const int idx = tid + j * 256;          // 0..1023
            const int r   = idx >> 4;               // 0..63
            const int c4  = (idx & 15) << 2;
            float4 kv = *reinterpret_cast<const float4*>(
                Kg + kbase + (s0 + r) * 512 + c4);
            *reinterpret_cast<uint4*>(&Ksm[r * KS + c4]) = cvt4(kv);
            float4 vv = *reinterpret_cast<const float4*>(
                Vg + vbase + (s0 + r) * 512 + c4);
            *reinterpret_cast<uint4*>(&Vsm[r * VS + c4]) = cvt4(vv);
        }
        __syncthreads();

        // ---- Scores (16x64 per warp) + exp + P store ----
        #pragma unroll
        for (int nf = 0; nf < 8; ++nf) {
            float C[4] = {0.0f, 0.0f, 0.0f, 0.0f};
            const uint32_t* kr = &Ksm[(nf * 8 + g) * KS];
            #pragma unroll
            for (int kc = 0; kc < 8; ++kc) {
                mma_tf32(C, Qa[kc], kr[kc * 8 + t], kr[kc * 8 + t + 4], C);
            }
            const float p0 = pexp(C[0]);
            const float p1 = pexp(C[1]);
            const float p2 = pexp(C[2]);
            const float p3 = pexp(C[3]);
            lsum0 += p0 + p1;
            lsum1 += p2 + p3;
            *reinterpret_cast<uint2*>(&Psm[(w * 16 + g) * PS + nf * 8 + 2 * t])
                = make_uint2(f2tf(p0), f2tf(p1));
            *reinterpret_cast<uint2*>(&Psm[(w * 16 + g + 8) * PS + nf * 8 + 2 * t])
                = make_uint2(f2tf(p2), f2tf(p3));
        }
        __syncwarp();   // P (warp-private rows) visible for A-layout reload

        // ---- O += P(16 x 64) * V(64 x 64) ----
        {
            const uint32_t* p0r = &Psm[(w * 16 + g) * PS];
            const uint32_t* p1r = p0r + 8 * PS;
            #pragma unroll
            for (int kc = 0; kc < 8; ++kc) {
                uint32_t Pa[4];
                Pa[0] = p0r[kc * 8 + t];
                Pa[1] = p1r[kc * 8 + t];
                Pa[2] = p0r[kc * 8 + t + 4];
                Pa[3] = p1r[kc * 8 + t + 4];
                const uint32_t* v0 = &Vsm[(kc * 8 + t) * VS];
                const uint32_t* v1 = v0 + 4 * VS;
                #pragma unroll
                for (int nf = 0; nf < 8; ++nf) {
                    mma_tf32(Oc[nf], Pa, v0[nf * 8 + g], v1[nf * 8 + g], Oc[nf]);
                }
            }
        }
        __syncwarp();   // PV reads done before next tile's P overwrite
    }

    // ---- Row-sum reduction across the 4 lanes of each quad ----
    #pragma unroll
    for (int off = 1; off <= 2; off <<= 1) {
        lsum0 += __shfl_xor_sync(0xffffffffu, lsum0, off);
        lsum1 += __shfl_xor_sync(0xffffffffu, lsum1, off);
    }
    const float inv0 = 1.0f / lsum0;
    const float inv1 = 1.0f / lsum1;

    // ---- Epilogue: normalize + store. O layout [BN, L, H, D]. ----
    const int m0 = l0 + w * 16 + g;
    float* o0 = Og + bn * (L_ * H_ * D_) + m0 * 512 + h * 64;
    float* o1 = o0 + 8 * 512;
    #pragma unroll
    for (int nf = 0; nf < 8; ++nf) {
        *reinterpret_cast<float2*>(o0 + nf * 8 + 2 * t)
            = make_float2(Oc[nf][0] * inv0, Oc[nf][1] * inv0);
        *reinterpret_cast<float2*>(o1 + nf * 8 + 2 * t)
            = make_float2(Oc[nf][2] * inv1, Oc[nf][3] * inv1);
    }
}

extern "C" void kernel_launch(void* const* d_in, const int* in_sizes, int n_in,
                              void* d_out, int out_size) {
    const float* Q = (const float*)d_in[0];
    const float* K = (const float*)d_in[1];
    const float* V = (const float*)d_in[2];
    float* O = (float*)d_out;

    cudaFuncSetAttribute(attn_hmma_tf32_kernel,
                         cudaFuncAttributeMaxDynamicSharedMemorySize, SMEM_BYTES);

    dim3 grid(L_ / M_TILE, B_ * N_ * H_);   // (4, 224)
    attn_hmma_tf32_kernel<<<grid, THREADS, SMEM_BYTES>>>(Q, K, V, O);
}